// round 7
// baseline (speedup 1.0000x reference)
#include <cuda_runtime.h>
#include <cuda_fp16.h>
#include <cstddef>

#define NN 100000
#define EE 1600000

// ---------------- device scratch (static allocation only) ----------------
__device__ __half g_hh [(size_t)NN * 64];   // per-layer transformed features (fp16)
__device__ float  g_x1 [(size_t)NN * 64];   // layer-1 output (fp32), later JK-max in place
__device__ float2 g_asrc[NN];
__device__ float2 g_adst[NN];
__device__ int    g_deg [NN];               // zero-initialized; re-zeroed by k_scan1 each call
__device__ int    g_rowptr[NN + 1];
__device__ int    g_cursor[NN];
__device__ int    g_csrc[EE];

// ---------------- CSR build ----------------
__global__ void k_hist(const int* __restrict__ ei) {
    int e4 = blockIdx.x * blockDim.x + threadIdx.x;
    if (e4 < EE / 4) {
        int4 d = ((const int4*)(ei + EE))[e4];
        atomicAdd(&g_deg[d.x], 1);
        atomicAdd(&g_deg[d.y], 1);
        atomicAdd(&g_deg[d.z], 1);
        atomicAdd(&g_deg[d.w], 1);
    }
}

__device__ __forceinline__ int blockScanEx(int v, int* ws, int nthreads) {
    int t = threadIdx.x;
    int lane = t & 31, wid = t >> 5;
    int x = v;
#pragma unroll
    for (int o = 1; o < 32; o <<= 1) {
        int y = __shfl_up_sync(0xffffffffu, x, o);
        if (lane >= o) x += y;
    }
    if (lane == 31) ws[wid] = x;
    __syncthreads();
    int nw = nthreads >> 5;
    if (wid == 0) {
        int s = (lane < nw) ? ws[lane] : 0;
#pragma unroll
        for (int o = 1; o < 32; o <<= 1) {
            int y = __shfl_up_sync(0xffffffffu, s, o);
            if (lane >= o) s += y;
        }
        if (lane < nw) ws[lane] = s;
    }
    __syncthreads();
    int off = (wid == 0) ? 0 : ws[wid - 1];
    return off + x - v;   // exclusive prefix
}

// Single-block fused scan: rowptr/cursor from g_deg, then re-zero g_deg so the
// next kernel_launch call (graph replay) starts from the same state.
__global__ void k_scan1() {
    __shared__ int ws[32];
    int t = threadIdx.x;                       // 1024 threads
    const int CH = (NN + 1023) / 1024;         // 98
    int b0 = t * CH;
    int b1 = b0 + CH; if (b1 > NN) b1 = NN;
    int s = 0;
    for (int i = b0; i < b1; i++) s += g_deg[i];
    int ex = blockScanEx(s, ws, 1024);
    int run = ex;
    for (int i = b0; i < b1; i++) {
        int d = g_deg[i];
        g_rowptr[i] = run;
        g_cursor[i] = run;
        g_deg[i] = 0;
        run += d;
    }
    if (t == 0) g_rowptr[NN] = EE;
}

__global__ void k_fill(const int* __restrict__ ei) {
    int e4 = blockIdx.x * blockDim.x + threadIdx.x;
    if (e4 < EE / 4) {
        int4 s = ((const int4*)ei)[e4];
        int4 d = ((const int4*)(ei + EE))[e4];
        g_csrc[atomicAdd(&g_cursor[d.x], 1)] = s.x;
        g_csrc[atomicAdd(&g_cursor[d.y], 1)] = s.y;
        g_csrc[atomicAdd(&g_cursor[d.z], 1)] = s.z;
        g_csrc[atomicAdd(&g_cursor[d.w], 1)] = s.w;
    }
}

// ---------------- dense GEMM (8x4 register tile, COUT=64, fp16 out) ----------
// 128 rows/block, 256 threads: rg = t/16 (8 rows each), cg = t%16 (4 cols each).
// Epilogue: fp16 store of h + fused attention logits -> g_asrc/g_adst.
template <int FIN>
__global__ void k_gemm64(const float* __restrict__ X, const float* __restrict__ W,
                         const float* __restrict__ a_s, const float* __restrict__ a_d) {
    constexpr int COUT = 64;
    constexpr int ROWS = 128;
    constexpr int KC = 32;
    __shared__ __align__(16) float sX[KC][ROWS + 4];
    __shared__ __align__(16) float sW[KC][COUT];

    int t = threadIdx.x;
    int rg = t >> 4, cg = t & 15;
    int row0 = blockIdx.x * ROWS;
    float acc[8][4] = {};

    for (int kc = 0; kc < FIN; kc += KC) {
#pragma unroll
        for (int it = 0; it < ROWS * KC / 4 / 256; it++) {
            int idx = t + it * 256;
            int r = idx >> 3, kq = idx & 7;
            int gr = row0 + r;
            float4 v = make_float4(0.f, 0.f, 0.f, 0.f);
            if (gr < NN) v = *(const float4*)&X[(size_t)gr * FIN + kc + kq * 4];
            sX[kq * 4 + 0][r] = v.x;
            sX[kq * 4 + 1][r] = v.y;
            sX[kq * 4 + 2][r] = v.z;
            sX[kq * 4 + 3][r] = v.w;
        }
#pragma unroll
        for (int it = 0; it < KC * COUT / 4 / 256; it++) {
            int idx = t + it * 256;
            int k = idx >> 4, cq = idx & 15;
            *(float4*)&sW[k][cq * 4] = *(const float4*)&W[(size_t)(kc + k) * COUT + cq * 4];
        }
        __syncthreads();
#pragma unroll
        for (int k = 0; k < KC; k++) {
            float4 xa = *(const float4*)&sX[k][rg * 8];
            float4 xb = *(const float4*)&sX[k][rg * 8 + 4];
            float4 wv = *(const float4*)&sW[k][cg * 4];
            float xr[8] = {xa.x, xa.y, xa.z, xa.w, xb.x, xb.y, xb.z, xb.w};
#pragma unroll
            for (int i = 0; i < 8; i++) {
                acc[i][0] += xr[i] * wv.x;
                acc[i][1] += xr[i] * wv.y;
                acc[i][2] += xr[i] * wv.z;
                acc[i][3] += xr[i] * wv.w;
            }
        }
        __syncthreads();
    }

#pragma unroll
    for (int i = 0; i < 8; i++) {
        int gr = row0 + rg * 8 + i;
        if (gr < NN) {
            __half2 a01 = __floats2half2_rn(acc[i][0], acc[i][1]);
            __half2 a23 = __floats2half2_rn(acc[i][2], acc[i][3]);
            __half2* hp = (__half2*)(g_hh + (size_t)gr * COUT);
            hp[cg * 2]     = a01;
            hp[cg * 2 + 1] = a23;
        }
    }

    // fused attention logits (fp32)
    float as4[4], ad4[4];
#pragma unroll
    for (int j = 0; j < 4; j++) { as4[j] = a_s[cg * 4 + j]; ad4[j] = a_d[cg * 4 + j]; }
#pragma unroll
    for (int i = 0; i < 8; i++) {
        float ps = 0.f, pd = 0.f;
#pragma unroll
        for (int j = 0; j < 4; j++) { ps += acc[i][j] * as4[j]; pd += acc[i][j] * ad4[j]; }
#pragma unroll
        for (int o = 4; o; o >>= 1) {
            ps += __shfl_xor_sync(0xffffffffu, ps, o);
            pd += __shfl_xor_sync(0xffffffffu, pd, o);
        }
        float ps1 = __shfl_xor_sync(0xffffffffu, ps, 8);
        float pd1 = __shfl_xor_sync(0xffffffffu, pd, 8);
        if (cg == 0) {
            int gr = row0 + rg * 8 + i;
            if (gr < NN) {
                g_asrc[gr] = make_float2(ps, ps1);
                g_adst[gr] = make_float2(pd, pd1);
            }
        }
    }
}

// ---------------- final GEMM (4x4 tile, COUT=40) -----------------------------
__global__ void k_gemmf(const float* __restrict__ X, const float* __restrict__ W,
                        const float* __restrict__ bias, float* __restrict__ Y) {
    constexpr int FIN = 64, COUT = 40, RG = 16, CG = 10;
    constexpr int ROWS = RG * 4, KC = 32, NT = RG * CG;
    __shared__ __align__(16) float sX[KC][ROWS + 4];
    __shared__ __align__(16) float sW[KC][COUT];

    int t = threadIdx.x;
    int rg = t / CG, cg = t % CG;
    int row0 = blockIdx.x * ROWS;
    float acc[4][4] = {};

    for (int kc = 0; kc < FIN; kc += KC) {
        for (int idx = t; idx < ROWS * KC; idx += NT) {
            int r = idx >> 5, k = idx & 31;
            int gr = row0 + r;
            sX[k][r] = (gr < NN) ? X[(size_t)gr * FIN + kc + k] : 0.f;
        }
        for (int idx = t; idx < KC * COUT; idx += NT) {
            int k = idx / COUT, c = idx % COUT;
            sW[k][c] = W[(size_t)(kc + k) * COUT + c];
        }
        __syncthreads();
#pragma unroll
        for (int k = 0; k < KC; k++) {
            float4 xv = *(const float4*)&sX[k][rg * 4];
            float4 wv = *(const float4*)&sW[k][cg * 4];
            float xr[4] = {xv.x, xv.y, xv.z, xv.w};
#pragma unroll
            for (int i = 0; i < 4; i++) {
                acc[i][0] += xr[i] * wv.x;
                acc[i][1] += xr[i] * wv.y;
                acc[i][2] += xr[i] * wv.z;
                acc[i][3] += xr[i] * wv.w;
            }
        }
        __syncthreads();
    }

    float b0 = bias[cg * 4], b1 = bias[cg * 4 + 1], b2 = bias[cg * 4 + 2], b3 = bias[cg * 4 + 3];
#pragma unroll
    for (int i = 0; i < 4; i++) {
        int gr = row0 + rg * 4 + i;
        if (gr < NN) {
            float4 o;
            o.x = acc[i][0] + b0; o.y = acc[i][1] + b1;
            o.z = acc[i][2] + b2; o.w = acc[i][3] + b3;
            *(float4*)&Y[(size_t)gr * COUT + cg * 4] = o;
        }
    }
}

__device__ __forceinline__ float lrelu(float x) { return x > 0.f ? x : 0.2f * x; }

// ---------------- single-pass softmax aggregation, one warp per destination ------
// Batch of 32 edges staged in smem; inner loop = broadcast LDS.64 + half2 LDG + 2 FMA.
template <int LAYER>
__global__ void k_agg(const float* __restrict__ bias,
                      const float* __restrict__ bgamma, const float* __restrict__ bbeta,
                      const float* __restrict__ bmean,  const float* __restrict__ bvar) {
    __shared__ __align__(16) float2 buf[8][32][2];   // [warp][edge][half] = (srcbits, w_half)

    int w = (blockIdx.x * blockDim.x + threadIdx.x) >> 5;
    if (w >= NN) return;
    int lane = threadIdx.x & 31;
    int wid = threadIdx.x >> 5;
    int half = lane >> 4;

    float2 ad = g_adst[w];
    int s0 = g_rowptr[w], s1 = g_rowptr[w + 1];

    float accx = 0.f, accy = 0.f;
    float dd0 = 0.f, dd1 = 0.f;

    const __half2* hbase = (const __half2*)g_hh;

    for (int base = s0; base < s1; base += 32) {
        int n = s1 - base; if (n > 32) n = 32;
        if (lane < n) {
            int s = g_csrc[base + lane];                  // coalesced
            float2 a = g_asrc[s];                         // parallel gather
            float w0 = __expf(lrelu(a.x + ad.x));
            float w1 = __expf(lrelu(a.y + ad.y));
            dd0 += w0; dd1 += w1;
            float sb = __int_as_float(s);
            buf[wid][lane][0] = make_float2(sb, w0);
            buf[wid][lane][1] = make_float2(sb, w1);
        }
        __syncwarp();
#pragma unroll 4
        for (int k = 0; k < n; k++) {
            float2 e = buf[wid][k][half];                 // broadcast LDS.64
            int ss = __float_as_int(e.x);
            float2 hv = __half22float2(hbase[(size_t)ss * 32 + lane]);
            accx += e.y * hv.x;
            accy += e.y * hv.y;
        }
        __syncwarp();
    }

    // self loop + lane reduction of denominators
    {
        float2 asn = g_asrc[w];
        float w0 = __expf(lrelu(asn.x + ad.x));
        float w1 = __expf(lrelu(asn.y + ad.y));
        float2 hv = __half22float2(hbase[(size_t)w * 32 + lane]);
        float ww = (lane < 16) ? w0 : w1;
        accx += ww * hv.x; accy += ww * hv.y;
#pragma unroll
        for (int o = 16; o; o >>= 1) {
            dd0 += __shfl_xor_sync(0xffffffffu, dd0, o);
            dd1 += __shfl_xor_sync(0xffffffffu, dd1, o);
        }
        dd0 += w0; dd1 += w1;
    }

    float inv = (lane < 16) ? (1.f / (dd0 + 1e-16f)) : (1.f / (dd1 + 1e-16f));
    int c0 = 2 * lane, c1 = c0 + 1;
    float o0 = accx * inv + bias[c0];
    float o1 = accy * inv + bias[c1];

    if (LAYER == 1) {
        float sc0 = bgamma[c0] * rsqrtf(bvar[c0] + 1e-5f);
        float sc1 = bgamma[c1] * rsqrtf(bvar[c1] + 1e-5f);
        float y0 = (o0 - bmean[c0]) * sc0 + bbeta[c0];
        float y1 = (o1 - bmean[c1]) * sc1 + bbeta[c1];
        y0 = y0 > 0.f ? y0 : expm1f(y0);
        y1 = y1 > 0.f ? y1 : expm1f(y1);
        *(float2*)(g_x1 + (size_t)w * 64 + c0) = make_float2(y0, y1);
    } else {
        float2* p = (float2*)(g_x1 + (size_t)w * 64 + c0);
        float2 v = *p;
        v.x = fmaxf(v.x, o0);
        v.y = fmaxf(v.y, o1);
        *p = v;
    }
}

// ---------------- launch ----------------
extern "C" void kernel_launch(void* const* d_in, const int* in_sizes, int n_in,
                              void* d_out, int out_size) {
    const float* node_feat = (const float*)d_in[0];
    const int*   ei        = (const int*)  d_in[1];
    const float* W1        = (const float*)d_in[2];
    const float* as1       = (const float*)d_in[3];
    const float* ad1       = (const float*)d_in[4];
    const float* b1        = (const float*)d_in[5];
    const float* bng       = (const float*)d_in[6];
    const float* bnb       = (const float*)d_in[7];
    const float* bnm       = (const float*)d_in[8];
    const float* bnv       = (const float*)d_in[9];
    const float* W2        = (const float*)d_in[10];
    const float* as2       = (const float*)d_in[11];
    const float* ad2       = (const float*)d_in[12];
    const float* b2        = (const float*)d_in[13];
    const float* Wf        = (const float*)d_in[14];
    const float* bf        = (const float*)d_in[15];
    float* out = (float*)d_out;

    float* px1 = nullptr;
    cudaGetSymbolAddress((void**)&px1, g_x1);

    const int eb4 = (EE / 4 + 255) / 256;
    const int ab = (NN + 7) / 8;       // warp-per-node kernels, 8 warps/block
    const int gb = (NN + 127) / 128;   // gemm64 blocks
    const int fb = (NN + 63) / 64;     // final gemm blocks

    // CSR build (g_deg is zero on entry: zero-initialized at load, re-zeroed by k_scan1)
    k_hist<<<eb4, 256>>>(ei);          // launch 1
    k_scan1<<<1, 1024>>>();            // launch 2
    k_fill<<<eb4, 256>>>(ei);          // launch 3

    // Layer 1 (gemm is launch 4 -> ncu profile target)
    k_gemm64<128><<<gb, 256>>>(node_feat, W1, as1, ad1);
    k_agg<1><<<ab, 256>>>(b1, bng, bnb, bnm, bnv);

    // Layer 2
    k_gemm64<64><<<gb, 256>>>(px1, W2, as2, ad2);
    k_agg<2><<<ab, 256>>>(b2, nullptr, nullptr, nullptr, nullptr);

    // Final projection on JK-max output
    k_gemmf<<<fb, 160>>>(px1, Wf, bf, out);
}

// round 11
// speedup vs baseline: 1.3757x; 1.3757x over previous
#include <cuda_runtime.h>
#include <cuda_fp16.h>
#include <cstddef>

#define NN 100000
#define EE 1600000

// ---------------- device scratch (static allocation only) ----------------
__device__ __half g_hh [(size_t)NN * 64];   // per-layer transformed features (fp16)
__device__ float  g_x1 [(size_t)NN * 64];   // layer-1 output (fp32), later JK-max in place
__device__ float2 g_asrc[NN];
__device__ float2 g_adst[NN];
__device__ int    g_deg [NN];               // zero-initialized; re-zeroed by k_scan1 each call
__device__ int    g_rowptr[NN + 1];
__device__ int    g_cursor[NN];
__device__ int    g_csrc[EE];

// ---------------- CSR build ----------------
__global__ void k_hist(const int* __restrict__ ei) {
    int e4 = blockIdx.x * blockDim.x + threadIdx.x;
    if (e4 < EE / 4) {
        int4 d = ((const int4*)(ei + EE))[e4];
        atomicAdd(&g_deg[d.x], 1);
        atomicAdd(&g_deg[d.y], 1);
        atomicAdd(&g_deg[d.z], 1);
        atomicAdd(&g_deg[d.w], 1);
    }
}

// Single-block fused scan, COALESCED: warp w owns [w*3125, (w+1)*3125), iterated
// in 32-wide tiles with a shfl scan per tile. Re-zeroes g_deg for the next call.
__global__ void k_scan1() {
    __shared__ int wtot[32];
    int t = threadIdx.x;                 // 1024 threads = 32 warps
    int lane = t & 31, wid = t >> 5;
    const int CHUNK = NN / 32;           // 3125 exactly
    int base = wid * CHUNK;
    int end = base + CHUNK;

    // phase A: per-warp sequential scan with coalesced tiles; store local excl prefix
    int running = 0;
    for (int i0 = base; i0 < end; i0 += 32) {
        int i = i0 + lane;
        int v = (i < end) ? g_deg[i] : 0;
        int x = v;
#pragma unroll
        for (int o = 1; o < 32; o <<= 1) {
            int y = __shfl_up_sync(0xffffffffu, x, o);
            if (lane >= o) x += y;
        }
        if (i < end) g_rowptr[i] = running + x - v;
        running += __shfl_sync(0xffffffffu, x, 31);
    }
    if (lane == 0) wtot[wid] = running;
    __syncthreads();

    // warp totals -> exclusive offsets
    if (wid == 0) {
        int v = wtot[lane];
        int x = v;
#pragma unroll
        for (int o = 1; o < 32; o <<= 1) {
            int y = __shfl_up_sync(0xffffffffu, x, o);
            if (lane >= o) x += y;
        }
        wtot[lane] = x - v;
    }
    __syncthreads();

    // phase B: add offset, mirror to cursor, zero deg (all coalesced)
    int off = wtot[wid];
    for (int i0 = base; i0 < end; i0 += 32) {
        int i = i0 + lane;
        if (i < end) {
            int val = g_rowptr[i] + off;
            g_rowptr[i] = val;
            g_cursor[i] = val;
            g_deg[i] = 0;
        }
    }
    if (t == 0) g_rowptr[NN] = EE;
}

__global__ void k_fill(const int* __restrict__ ei) {
    int e4 = blockIdx.x * blockDim.x + threadIdx.x;
    if (e4 < EE / 4) {
        int4 s = ((const int4*)ei)[e4];
        int4 d = ((const int4*)(ei + EE))[e4];
        g_csrc[atomicAdd(&g_cursor[d.x], 1)] = s.x;
        g_csrc[atomicAdd(&g_cursor[d.y], 1)] = s.y;
        g_csrc[atomicAdd(&g_cursor[d.z], 1)] = s.z;
        g_csrc[atomicAdd(&g_cursor[d.w], 1)] = s.w;
    }
}

// ---------------- dense GEMM (8x4 register tile, COUT=64, fp16 out) ----------
// 128 rows/block, 256 threads: rg = t/16 (8 rows each), cg = t%16 (4 cols each).
// Epilogue: fp16 store of h + fused attention logits -> g_asrc/g_adst.
template <int FIN>
__global__ void k_gemm64(const float* __restrict__ X, const float* __restrict__ W,
                         const float* __restrict__ a_s, const float* __restrict__ a_d) {
    constexpr int COUT = 64;
    constexpr int ROWS = 128;
    constexpr int KC = 32;
    __shared__ __align__(16) float sX[KC][ROWS + 4];
    __shared__ __align__(16) float sW[KC][COUT];

    int t = threadIdx.x;
    int rg = t >> 4, cg = t & 15;
    int row0 = blockIdx.x * ROWS;
    float acc[8][4] = {};

    for (int kc = 0; kc < FIN; kc += KC) {
#pragma unroll
        for (int it = 0; it < ROWS * KC / 4 / 256; it++) {
            int idx = t + it * 256;
            int r = idx >> 3, kq = idx & 7;
            int gr = row0 + r;
            float4 v = make_float4(0.f, 0.f, 0.f, 0.f);
            if (gr < NN) v = *(const float4*)&X[(size_t)gr * FIN + kc + kq * 4];
            sX[kq * 4 + 0][r] = v.x;
            sX[kq * 4 + 1][r] = v.y;
            sX[kq * 4 + 2][r] = v.z;
            sX[kq * 4 + 3][r] = v.w;
        }
#pragma unroll
        for (int it = 0; it < KC * COUT / 4 / 256; it++) {
            int idx = t + it * 256;
            int k = idx >> 4, cq = idx & 15;
            *(float4*)&sW[k][cq * 4] = *(const float4*)&W[(size_t)(kc + k) * COUT + cq * 4];
        }
        __syncthreads();
#pragma unroll
        for (int k = 0; k < KC; k++) {
            float4 xa = *(const float4*)&sX[k][rg * 8];
            float4 xb = *(const float4*)&sX[k][rg * 8 + 4];
            float4 wv = *(const float4*)&sW[k][cg * 4];
            float xr[8] = {xa.x, xa.y, xa.z, xa.w, xb.x, xb.y, xb.z, xb.w};
#pragma unroll
            for (int i = 0; i < 8; i++) {
                acc[i][0] += xr[i] * wv.x;
                acc[i][1] += xr[i] * wv.y;
                acc[i][2] += xr[i] * wv.z;
                acc[i][3] += xr[i] * wv.w;
            }
        }
        __syncthreads();
    }

#pragma unroll
    for (int i = 0; i < 8; i++) {
        int gr = row0 + rg * 8 + i;
        if (gr < NN) {
            __half2 a01 = __floats2half2_rn(acc[i][0], acc[i][1]);
            __half2 a23 = __floats2half2_rn(acc[i][2], acc[i][3]);
            __half2* hp = (__half2*)(g_hh + (size_t)gr * COUT);
            hp[cg * 2]     = a01;
            hp[cg * 2 + 1] = a23;
        }
    }

    // fused attention logits (fp32)
    float as4[4], ad4[4];
#pragma unroll
    for (int j = 0; j < 4; j++) { as4[j] = a_s[cg * 4 + j]; ad4[j] = a_d[cg * 4 + j]; }
#pragma unroll
    for (int i = 0; i < 8; i++) {
        float ps = 0.f, pd = 0.f;
#pragma unroll
        for (int j = 0; j < 4; j++) { ps += acc[i][j] * as4[j]; pd += acc[i][j] * ad4[j]; }
#pragma unroll
        for (int o = 4; o; o >>= 1) {
            ps += __shfl_xor_sync(0xffffffffu, ps, o);
            pd += __shfl_xor_sync(0xffffffffu, pd, o);
        }
        float ps1 = __shfl_xor_sync(0xffffffffu, ps, 8);
        float pd1 = __shfl_xor_sync(0xffffffffu, pd, 8);
        if (cg == 0) {
            int gr = row0 + rg * 8 + i;
            if (gr < NN) {
                g_asrc[gr] = make_float2(ps, ps1);
                g_adst[gr] = make_float2(pd, pd1);
            }
        }
    }
}

// ---------------- final GEMM (4x4 tile, COUT=40) -----------------------------
__global__ void k_gemmf(const float* __restrict__ X, const float* __restrict__ W,
                        const float* __restrict__ bias, float* __restrict__ Y) {
    constexpr int FIN = 64, COUT = 40, RG = 16, CG = 10;
    constexpr int ROWS = RG * 4, KC = 32, NT = RG * CG;
    __shared__ __align__(16) float sX[KC][ROWS + 4];
    __shared__ __align__(16) float sW[KC][COUT];

    int t = threadIdx.x;
    int rg = t / CG, cg = t % CG;
    int row0 = blockIdx.x * ROWS;
    float acc[4][4] = {};

    for (int kc = 0; kc < FIN; kc += KC) {
        for (int idx = t; idx < ROWS * KC; idx += NT) {
            int r = idx >> 5, k = idx & 31;
            int gr = row0 + r;
            sX[k][r] = (gr < NN) ? X[(size_t)gr * FIN + kc + k] : 0.f;
        }
        for (int idx = t; idx < KC * COUT; idx += NT) {
            int k = idx / COUT, c = idx % COUT;
            sW[k][c] = W[(size_t)(kc + k) * COUT + c];
        }
        __syncthreads();
#pragma unroll
        for (int k = 0; k < KC; k++) {
            float4 xv = *(const float4*)&sX[k][rg * 4];
            float4 wv = *(const float4*)&sW[k][cg * 4];
            float xr[4] = {xv.x, xv.y, xv.z, xv.w};
#pragma unroll
            for (int i = 0; i < 4; i++) {
                acc[i][0] += xr[i] * wv.x;
                acc[i][1] += xr[i] * wv.y;
                acc[i][2] += xr[i] * wv.z;
                acc[i][3] += xr[i] * wv.w;
            }
        }
        __syncthreads();
    }

    float b0 = bias[cg * 4], b1 = bias[cg * 4 + 1], b2 = bias[cg * 4 + 2], b3 = bias[cg * 4 + 3];
#pragma unroll
    for (int i = 0; i < 4; i++) {
        int gr = row0 + rg * 4 + i;
        if (gr < NN) {
            float4 o;
            o.x = acc[i][0] + b0; o.y = acc[i][1] + b1;
            o.z = acc[i][2] + b2; o.w = acc[i][3] + b3;
            *(float4*)&Y[(size_t)gr * COUT + cg * 4] = o;
        }
    }
}

__device__ __forceinline__ float lrelu(float x) { return x > 0.f ? x : 0.2f * x; }

// ---------------- single-pass softmax aggregation, one warp per destination ------
// Batch of 32 edges staged in smem; inner loop = broadcast LDS.64 + half2 LDG + 2 FMA.
template <int LAYER>
__global__ void k_agg(const float* __restrict__ bias,
                      const float* __restrict__ bgamma, const float* __restrict__ bbeta,
                      const float* __restrict__ bmean,  const float* __restrict__ bvar) {
    __shared__ __align__(16) float2 buf[8][32][2];   // [warp][edge][half] = (srcbits, w_half)

    int w = (blockIdx.x * blockDim.x + threadIdx.x) >> 5;
    if (w >= NN) return;
    int lane = threadIdx.x & 31;
    int wid = threadIdx.x >> 5;
    int half = lane >> 4;

    float2 ad = g_adst[w];
    int s0 = g_rowptr[w], s1 = g_rowptr[w + 1];

    float accx = 0.f, accy = 0.f;
    float dd0 = 0.f, dd1 = 0.f;

    const __half2* hbase = (const __half2*)g_hh;

    for (int base = s0; base < s1; base += 32) {
        int n = s1 - base; if (n > 32) n = 32;
        if (lane < n) {
            int s = g_csrc[base + lane];                  // coalesced
            float2 a = g_asrc[s];                         // parallel gather
            float w0 = __expf(lrelu(a.x + ad.x));
            float w1 = __expf(lrelu(a.y + ad.y));
            dd0 += w0; dd1 += w1;
            float sb = __int_as_float(s);
            buf[wid][lane][0] = make_float2(sb, w0);
            buf[wid][lane][1] = make_float2(sb, w1);
        }
        __syncwarp();
#pragma unroll 4
        for (int k = 0; k < n; k++) {
            float2 e = buf[wid][k][half];                 // broadcast LDS.64
            int ss = __float_as_int(e.x);
            float2 hv = __half22float2(hbase[(size_t)ss * 32 + lane]);
            accx += e.y * hv.x;
            accy += e.y * hv.y;
        }
        __syncwarp();
    }

    // self loop + lane reduction of denominators
    {
        float2 asn = g_asrc[w];
        float w0 = __expf(lrelu(asn.x + ad.x));
        float w1 = __expf(lrelu(asn.y + ad.y));
        float2 hv = __half22float2(hbase[(size_t)w * 32 + lane]);
        float ww = (lane < 16) ? w0 : w1;
        accx += ww * hv.x; accy += ww * hv.y;
#pragma unroll
        for (int o = 16; o; o >>= 1) {
            dd0 += __shfl_xor_sync(0xffffffffu, dd0, o);
            dd1 += __shfl_xor_sync(0xffffffffu, dd1, o);
        }
        dd0 += w0; dd1 += w1;
    }

    float inv = (lane < 16) ? (1.f / (dd0 + 1e-16f)) : (1.f / (dd1 + 1e-16f));
    int c0 = 2 * lane, c1 = c0 + 1;
    float o0 = accx * inv + bias[c0];
    float o1 = accy * inv + bias[c1];

    if (LAYER == 1) {
        float sc0 = bgamma[c0] * rsqrtf(bvar[c0] + 1e-5f);
        float sc1 = bgamma[c1] * rsqrtf(bvar[c1] + 1e-5f);
        float y0 = (o0 - bmean[c0]) * sc0 + bbeta[c0];
        float y1 = (o1 - bmean[c1]) * sc1 + bbeta[c1];
        y0 = y0 > 0.f ? y0 : expm1f(y0);
        y1 = y1 > 0.f ? y1 : expm1f(y1);
        *(float2*)(g_x1 + (size_t)w * 64 + c0) = make_float2(y0, y1);
    } else {
        float2* p = (float2*)(g_x1 + (size_t)w * 64 + c0);
        float2 v = *p;
        v.x = fmaxf(v.x, o0);
        v.y = fmaxf(v.y, o1);
        *p = v;
    }
}

// ---------------- launch ----------------
extern "C" void kernel_launch(void* const* d_in, const int* in_sizes, int n_in,
                              void* d_out, int out_size) {
    const float* node_feat = (const float*)d_in[0];
    const int*   ei        = (const int*)  d_in[1];
    const float* W1        = (const float*)d_in[2];
    const float* as1       = (const float*)d_in[3];
    const float* ad1       = (const float*)d_in[4];
    const float* b1        = (const float*)d_in[5];
    const float* bng       = (const float*)d_in[6];
    const float* bnb       = (const float*)d_in[7];
    const float* bnm       = (const float*)d_in[8];
    const float* bnv       = (const float*)d_in[9];
    const float* W2        = (const float*)d_in[10];
    const float* as2       = (const float*)d_in[11];
    const float* ad2       = (const float*)d_in[12];
    const float* b2        = (const float*)d_in[13];
    const float* Wf        = (const float*)d_in[14];
    const float* bf        = (const float*)d_in[15];
    float* out = (float*)d_out;

    float* px1 = nullptr;
    cudaGetSymbolAddress((void**)&px1, g_x1);

    const int eb4 = (EE / 4 + 255) / 256;
    const int ab = (NN + 7) / 8;       // warp-per-node kernels, 8 warps/block
    const int gb = (NN + 127) / 128;   // gemm64 blocks
    const int fb = (NN + 63) / 64;     // final gemm blocks

    // CSR build (g_deg zero on entry: zero-init at load, re-zeroed by k_scan1)
    k_hist<<<eb4, 256>>>(ei);          // launch 1
    k_scan1<<<1, 1024>>>();            // launch 2
    k_fill<<<eb4, 256>>>(ei);          // launch 3

    // Layer 1 (gemm is launch 4 -> ncu profile target)
    k_gemm64<128><<<gb, 256>>>(node_feat, W1, as1, ad1);
    k_agg<1><<<ab, 256>>>(b1, bng, bnb, bnm, bnv);

    // Layer 2
    k_gemm64<64><<<gb, 256>>>(px1, W2, as2, ad2);
    k_agg<2><<<ab, 256>>>(b2, nullptr, nullptr, nullptr, nullptr);

    // Final projection on JK-max output
    k_gemmf<<<fb, 160>>>(px1, Wf, bf, out);
}

// round 13
// speedup vs baseline: 2.2779x; 1.6558x over previous
#include <cuda_runtime.h>
#include <cuda_fp16.h>
#include <cstddef>
#include <cstdint>

#define NN 100000
#define EE 1600000

// ---------------- device scratch (static allocation only) ----------------
__device__ float  g_h  [(size_t)NN * 64];   // per-layer transformed features (fp32)
__device__ float  g_x1 [(size_t)NN * 64];   // layer-1 output, later JK-max in place
__device__ float2 g_asrc[NN];
__device__ float2 g_adst[NN];
__device__ int    g_deg [NN];
__device__ int    g_rowptr[NN + 1];
__device__ int    g_cursor[NN];
__device__ int    g_bsum[256];
__device__ int    g_csrc[EE];

// ---------------- CSR build ----------------
__global__ void k_hist(const int* __restrict__ ei) {
    int e4 = blockIdx.x * blockDim.x + threadIdx.x;
    if (e4 < EE / 4) {
        int4 d = ((const int4*)(ei + EE))[e4];
        atomicAdd(&g_deg[d.x], 1);
        atomicAdd(&g_deg[d.y], 1);
        atomicAdd(&g_deg[d.z], 1);
        atomicAdd(&g_deg[d.w], 1);
    }
}

__device__ __forceinline__ int blockScanEx(int v, int* ws, int nthreads) {
    int t = threadIdx.x;
    int lane = t & 31, wid = t >> 5;
    int x = v;
#pragma unroll
    for (int o = 1; o < 32; o <<= 1) {
        int y = __shfl_up_sync(0xffffffffu, x, o);
        if (lane >= o) x += y;
    }
    if (lane == 31) ws[wid] = x;
    __syncthreads();
    int nw = nthreads >> 5;
    if (wid == 0) {
        int s = (lane < nw) ? ws[lane] : 0;
#pragma unroll
        for (int o = 1; o < 32; o <<= 1) {
            int y = __shfl_up_sync(0xffffffffu, s, o);
            if (lane >= o) s += y;
        }
        if (lane < nw) ws[lane] = s;
    }
    __syncthreads();
    int off = (wid == 0) ? 0 : ws[wid - 1];
    return off + x - v;   // exclusive prefix
}

__global__ void k_scanA() {
    __shared__ int ws[32];
    int t = threadIdx.x;
    int i = blockIdx.x * 512 + t;
    int v = (i < NN) ? g_deg[i] : 0;
    int ex = blockScanEx(v, ws, 512);
    if (i < NN) g_rowptr[i] = ex;
    if (t == 511) g_bsum[blockIdx.x] = ex + v;
}

__global__ void k_scanB(int nb) {
    __shared__ int ws[32];
    int t = threadIdx.x;
    int v = (t < nb) ? g_bsum[t] : 0;
    int ex = blockScanEx(v, ws, 256);
    if (t < nb) g_bsum[t] = ex;
}

__global__ void k_scanC() {
    int i = blockIdx.x * 512 + threadIdx.x;
    if (i < NN) {
        int val = g_rowptr[i] + g_bsum[blockIdx.x];
        g_rowptr[i] = val;
        g_cursor[i] = val;
    }
    if (i == 0) g_rowptr[NN] = EE;
}

__global__ void k_fill(const int* __restrict__ ei) {
    int e4 = blockIdx.x * blockDim.x + threadIdx.x;
    if (e4 < EE / 4) {
        int4 s = ((const int4*)ei)[e4];
        int4 d = ((const int4*)(ei + EE))[e4];
        g_csrc[atomicAdd(&g_cursor[d.x], 1)] = s.x;
        g_csrc[atomicAdd(&g_cursor[d.y], 1)] = s.y;
        g_csrc[atomicAdd(&g_cursor[d.z], 1)] = s.z;
        g_csrc[atomicAdd(&g_cursor[d.w], 1)] = s.w;
    }
}

// ---------------- tensor-core GEMM (m16n8k16 fp16 -> fp32), COUT=64 ----------
// 128 rows x 64 cols per block, 256 threads = 8 warps (4 m-groups x 2 n-groups).
// Each warp: 32x32 tile = 2 m-tiles(16) x 4 n-tiles(8). fp32 h out + fused alphas.
__device__ __forceinline__ void ldsm_x4(uint32_t& r0, uint32_t& r1, uint32_t& r2, uint32_t& r3, uint32_t addr) {
    asm volatile("ldmatrix.sync.aligned.m8n8.x4.shared.b16 {%0,%1,%2,%3}, [%4];"
                 : "=r"(r0), "=r"(r1), "=r"(r2), "=r"(r3) : "r"(addr));
}
__device__ __forceinline__ void ldsm_x2t(uint32_t& r0, uint32_t& r1, uint32_t addr) {
    asm volatile("ldmatrix.sync.aligned.m8n8.x2.trans.shared.b16 {%0,%1}, [%2];"
                 : "=r"(r0), "=r"(r1) : "r"(addr));
}
__device__ __forceinline__ void mma16816(float (&d)[4], const uint32_t (&a)[4], uint32_t b0, uint32_t b1) {
    asm volatile("mma.sync.aligned.m16n8k16.row.col.f32.f16.f16.f32 "
                 "{%0,%1,%2,%3}, {%4,%5,%6,%7}, {%8,%9}, {%0,%1,%2,%3};"
                 : "+f"(d[0]), "+f"(d[1]), "+f"(d[2]), "+f"(d[3])
                 : "r"(a[0]), "r"(a[1]), "r"(a[2]), "r"(a[3]), "r"(b0), "r"(b1));
}

template <int FIN>
__global__ void k_gemm_mma(const float* __restrict__ X, const float* __restrict__ W,
                           const float* __restrict__ a_s, const float* __restrict__ a_d) {
    constexpr int COUT = 64, ROWS = 128, KC = 32;
    constexpr int SA_STR = 40;   // halfs per row (pad 8 -> conflict-free ldmatrix)
    constexpr int SW_STR = 72;   // halfs per row (pad 8)
    __shared__ __align__(16) __half sA[ROWS * SA_STR];   // [row][k]
    __shared__ __align__(16) __half sW[KC * SW_STR];     // [k][n]
    __shared__ float sAS[ROWS][2];
    __shared__ float sAD[ROWS][2];

    int t = threadIdx.x;
    int lane = t & 31, warp = t >> 5;
    int wm = warp >> 1, wn = warp & 1;
    int row0 = blockIdx.x * ROWS;

    float acc[2][4][4];
#pragma unroll
    for (int mt = 0; mt < 2; mt++)
#pragma unroll
        for (int nt = 0; nt < 4; nt++)
#pragma unroll
            for (int j = 0; j < 4; j++) acc[mt][nt][j] = 0.f;

    for (int kc = 0; kc < FIN; kc += KC) {
        // A tile: fp32 -> fp16, [row][k]
#pragma unroll
        for (int it = 0; it < 4; it++) {
            int idx = t + it * 256;          // 0..1023 quads
            int r = idx >> 3, kq = idx & 7;
            int gr = row0 + r;
            float4 v = make_float4(0.f, 0.f, 0.f, 0.f);
            if (gr < NN) v = *(const float4*)&X[(size_t)gr * FIN + kc + kq * 4];
            __half2 p0 = __floats2half2_rn(v.x, v.y);
            __half2 p1 = __floats2half2_rn(v.z, v.w);
            *(uint2*)(sA + r * SA_STR + kq * 4) =
                make_uint2(*(uint32_t*)&p0, *(uint32_t*)&p1);
        }
        // W tile: fp32 -> fp16, [k][n]
#pragma unroll
        for (int it = 0; it < 2; it++) {
            int idx = t + it * 256;          // 0..511 quads
            int k = idx >> 4, nq = idx & 15;
            float4 v = *(const float4*)&W[(size_t)(kc + k) * COUT + nq * 4];
            __half2 p0 = __floats2half2_rn(v.x, v.y);
            __half2 p1 = __floats2half2_rn(v.z, v.w);
            *(uint2*)(sW + k * SW_STR + nq * 4) =
                make_uint2(*(uint32_t*)&p0, *(uint32_t*)&p1);
        }
        __syncthreads();
#pragma unroll
        for (int km = 0; km < KC; km += 16) {
            uint32_t a[2][4], b[4][2];
#pragma unroll
            for (int mt = 0; mt < 2; mt++) {
                int row = wm * 32 + mt * 16 + (lane & 15);
                uint32_t addr = (uint32_t)__cvta_generic_to_shared(
                    sA + row * SA_STR + km + 8 * (lane >> 4));
                ldsm_x4(a[mt][0], a[mt][1], a[mt][2], a[mt][3], addr);
            }
#pragma unroll
            for (int nt = 0; nt < 4; nt++) {
                int l2 = lane & 15;
                int krow = km + (l2 & 7) + 8 * (l2 >> 3);
                uint32_t addr = (uint32_t)__cvta_generic_to_shared(
                    sW + krow * SW_STR + wn * 32 + nt * 8);
                ldsm_x2t(b[nt][0], b[nt][1], addr);
            }
#pragma unroll
            for (int mt = 0; mt < 2; mt++)
#pragma unroll
                for (int nt = 0; nt < 4; nt++)
                    mma16816(acc[mt][nt], a[mt], b[nt][0], b[nt][1]);
        }
        __syncthreads();
    }

    // D-frag: d0,d1 = (row qr, col 2*qc+{0,1}); d2,d3 = (row qr+8, same cols)
    int qr = lane >> 2, qc = lane & 3;

    // h out (fp32)
#pragma unroll
    for (int mt = 0; mt < 2; mt++) {
        int r0g = row0 + wm * 32 + mt * 16 + qr;
#pragma unroll
        for (int nt = 0; nt < 4; nt++) {
            int col = wn * 32 + nt * 8 + qc * 2;
            if (r0g < NN)
                *(float2*)&g_h[(size_t)r0g * 64 + col] = make_float2(acc[mt][nt][0], acc[mt][nt][1]);
            if (r0g + 8 < NN)
                *(float2*)&g_h[(size_t)(r0g + 8) * 64 + col] = make_float2(acc[mt][nt][2], acc[mt][nt][3]);
        }
    }

    // fused attention logits: this warp covers head `wn` (cols wn*32..wn*32+31)
    float as_[4][2], ad_[4][2];
#pragma unroll
    for (int nt = 0; nt < 4; nt++) {
        int col = wn * 32 + nt * 8 + qc * 2;
        as_[nt][0] = a_s[col]; as_[nt][1] = a_s[col + 1];
        ad_[nt][0] = a_d[col]; ad_[nt][1] = a_d[col + 1];
    }
#pragma unroll
    for (int mt = 0; mt < 2; mt++) {
        float ps0 = 0.f, ps1 = 0.f, pd0 = 0.f, pd1 = 0.f;
#pragma unroll
        for (int nt = 0; nt < 4; nt++) {
            ps0 += acc[mt][nt][0] * as_[nt][0] + acc[mt][nt][1] * as_[nt][1];
            ps1 += acc[mt][nt][2] * as_[nt][0] + acc[mt][nt][3] * as_[nt][1];
            pd0 += acc[mt][nt][0] * ad_[nt][0] + acc[mt][nt][1] * ad_[nt][1];
            pd1 += acc[mt][nt][2] * ad_[nt][0] + acc[mt][nt][3] * ad_[nt][1];
        }
#pragma unroll
        for (int o = 1; o < 4; o <<= 1) {
            ps0 += __shfl_xor_sync(0xffffffffu, ps0, o);
            ps1 += __shfl_xor_sync(0xffffffffu, ps1, o);
            pd0 += __shfl_xor_sync(0xffffffffu, pd0, o);
            pd1 += __shfl_xor_sync(0xffffffffu, pd1, o);
        }
        if (qc == 0) {
            int rl = wm * 32 + mt * 16 + qr;
            sAS[rl][wn] = ps0; sAS[rl + 8][wn] = ps1;
            sAD[rl][wn] = pd0; sAD[rl + 8][wn] = pd1;
        }
    }
    __syncthreads();
    if (t < ROWS) {
        int gr = row0 + t;
        if (gr < NN) {
            g_asrc[gr] = make_float2(sAS[t][0], sAS[t][1]);
            g_adst[gr] = make_float2(sAD[t][0], sAD[t][1]);
        }
    }
}

// ---------------- final GEMM (4x4 tile, COUT=40, fp32) -----------------------
__global__ void k_gemmf(const float* __restrict__ X, const float* __restrict__ W,
                        const float* __restrict__ bias, float* __restrict__ Y) {
    constexpr int FIN = 64, COUT = 40, RG = 16, CG = 10;
    constexpr int ROWS = RG * 4, KC = 32, NT = RG * CG;
    __shared__ __align__(16) float sX[KC][ROWS + 4];
    __shared__ __align__(16) float sW[KC][COUT];

    int t = threadIdx.x;
    int rg = t / CG, cg = t % CG;
    int row0 = blockIdx.x * ROWS;
    float acc[4][4] = {};

    for (int kc = 0; kc < FIN; kc += KC) {
        for (int idx = t; idx < ROWS * KC; idx += NT) {
            int r = idx >> 5, k = idx & 31;
            int gr = row0 + r;
            sX[k][r] = (gr < NN) ? X[(size_t)gr * FIN + kc + k] : 0.f;
        }
        for (int idx = t; idx < KC * COUT; idx += NT) {
            int k = idx / COUT, c = idx % COUT;
            sW[k][c] = W[(size_t)(kc + k) * COUT + c];
        }
        __syncthreads();
#pragma unroll
        for (int k = 0; k < KC; k++) {
            float4 xv = *(const float4*)&sX[k][rg * 4];
            float4 wv = *(const float4*)&sW[k][cg * 4];
            float xr[4] = {xv.x, xv.y, xv.z, xv.w};
#pragma unroll
            for (int i = 0; i < 4; i++) {
                acc[i][0] += xr[i] * wv.x;
                acc[i][1] += xr[i] * wv.y;
                acc[i][2] += xr[i] * wv.z;
                acc[i][3] += xr[i] * wv.w;
            }
        }
        __syncthreads();
    }

    float b0 = bias[cg * 4], b1 = bias[cg * 4 + 1], b2 = bias[cg * 4 + 2], b3 = bias[cg * 4 + 3];
#pragma unroll
    for (int i = 0; i < 4; i++) {
        int gr = row0 + rg * 4 + i;
        if (gr < NN) {
            float4 o;
            o.x = acc[i][0] + b0; o.y = acc[i][1] + b1;
            o.z = acc[i][2] + b2; o.w = acc[i][3] + b3;
            *(float4*)&Y[(size_t)gr * COUT + cg * 4] = o;
        }
    }
}

__device__ __forceinline__ float lrelu(float x) { return x > 0.f ? x : 0.2f * x; }

// ---------------- single-pass softmax aggregation, one warp per destination ------
template <int LAYER>
__global__ void k_agg(const float* __restrict__ bias,
                      const float* __restrict__ bgamma, const float* __restrict__ bbeta,
                      const float* __restrict__ bmean,  const float* __restrict__ bvar) {
    __shared__ __align__(16) float2 buf[8][32][2];   // [warp][edge][half] = (srcbits, w_half)

    int w = (blockIdx.x * blockDim.x + threadIdx.x) >> 5;
    if (w >= NN) return;
    int lane = threadIdx.x & 31;
    int wid = threadIdx.x >> 5;
    int half = lane >> 4;

    float2 ad = g_adst[w];
    int s0 = g_rowptr[w], s1 = g_rowptr[w + 1];

    float accx = 0.f, accy = 0.f;
    float dd0 = 0.f, dd1 = 0.f;

    for (int base = s0; base < s1; base += 32) {
        int n = s1 - base; if (n > 32) n = 32;
        if (lane < n) {
            int s = g_csrc[base + lane];                  // coalesced
            float2 a = g_asrc[s];                         // parallel gather
            float w0 = __expf(lrelu(a.x + ad.x));
            float w1 = __expf(lrelu(a.y + ad.y));
            dd0 += w0; dd1 += w1;
            float sb = __int_as_float(s);
            buf[wid][lane][0] = make_float2(sb, w0);
            buf[wid][lane][1] = make_float2(sb, w1);
        }
        __syncwarp();
#pragma unroll 2
        for (int k = 0; k < n; k++) {
            float2 e = buf[wid][k][half];                 // broadcast LDS.64
            int ss = __float_as_int(e.x);
            float2 hv = *(const float2*)(g_h + (size_t)ss * 64 + 2 * lane);
            accx += e.y * hv.x;
            accy += e.y * hv.y;
        }
        __syncwarp();
    }

    // self loop + lane reduction of denominators
    {
        float2 asn = g_asrc[w];
        float w0 = __expf(lrelu(asn.x + ad.x));
        float w1 = __expf(lrelu(asn.y + ad.y));
        float2 hv = *(const float2*)(g_h + (size_t)w * 64 + 2 * lane);
        float ww = (lane < 16) ? w0 : w1;
        accx += ww * hv.x; accy += ww * hv.y;
#pragma unroll
        for (int o = 16; o; o >>= 1) {
            dd0 += __shfl_xor_sync(0xffffffffu, dd0, o);
            dd1 += __shfl_xor_sync(0xffffffffu, dd1, o);
        }
        dd0 += w0; dd1 += w1;
    }

    float inv = (lane < 16) ? (1.f / (dd0 + 1e-16f)) : (1.f / (dd1 + 1e-16f));
    int c0 = 2 * lane, c1 = c0 + 1;
    float o0 = accx * inv + bias[c0];
    float o1 = accy * inv + bias[c1];

    if (LAYER == 1) {
        float sc0 = bgamma[c0] * rsqrtf(bvar[c0] + 1e-5f);
        float sc1 = bgamma[c1] * rsqrtf(bvar[c1] + 1e-5f);
        float y0 = (o0 - bmean[c0]) * sc0 + bbeta[c0];
        float y1 = (o1 - bmean[c1]) * sc1 + bbeta[c1];
        y0 = y0 > 0.f ? y0 : expm1f(y0);
        y1 = y1 > 0.f ? y1 : expm1f(y1);
        *(float2*)(g_x1 + (size_t)w * 64 + c0) = make_float2(y0, y1);
    } else {
        float2* p = (float2*)(g_x1 + (size_t)w * 64 + c0);
        float2 v = *p;
        v.x = fmaxf(v.x, o0);
        v.y = fmaxf(v.y, o1);
        *p = v;
    }
}

// ---------------- launch ----------------
extern "C" void kernel_launch(void* const* d_in, const int* in_sizes, int n_in,
                              void* d_out, int out_size) {
    const float* node_feat = (const float*)d_in[0];
    const int*   ei        = (const int*)  d_in[1];
    const float* W1        = (const float*)d_in[2];
    const float* as1       = (const float*)d_in[3];
    const float* ad1       = (const float*)d_in[4];
    const float* b1        = (const float*)d_in[5];
    const float* bng       = (const float*)d_in[6];
    const float* bnb       = (const float*)d_in[7];
    const float* bnm       = (const float*)d_in[8];
    const float* bnv       = (const float*)d_in[9];
    const float* W2        = (const float*)d_in[10];
    const float* as2       = (const float*)d_in[11];
    const float* ad2       = (const float*)d_in[12];
    const float* b2        = (const float*)d_in[13];
    const float* Wf        = (const float*)d_in[14];
    const float* bf        = (const float*)d_in[15];
    float* out = (float*)d_out;

    float *px1 = nullptr;
    int *pdeg = nullptr;
    cudaGetSymbolAddress((void**)&px1, g_x1);
    cudaGetSymbolAddress((void**)&pdeg, g_deg);

    const int eb4 = (EE / 4 + 255) / 256;
    const int nb = (NN + 511) / 512;   // 196 scan blocks
    const int ab = (NN + 7) / 8;       // warp-per-node kernels, 8 warps/block
    const int gb = (NN + 127) / 128;   // mma gemm blocks
    const int fb = (NN + 63) / 64;     // final gemm blocks

    // CSR build + layer-1 GEMM, ordered so the mma GEMM is kernel-launch #4 (ncu target)
    cudaMemsetAsync(pdeg, 0, NN * sizeof(int));
    k_hist<<<eb4, 256>>>(ei);                               // 1
    k_scanA<<<nb, 512>>>();                                 // 2
    k_scanB<<<1, 256>>>(nb);                                // 3
    k_gemm_mma<128><<<gb, 256>>>(node_feat, W1, as1, ad1);  // 4  <- profiled
    k_scanC<<<nb, 512>>>();                                 // 5
    k_fill<<<eb4, 256>>>(ei);                               // 6

    k_agg<1><<<ab, 256>>>(b1, bng, bnb, bnm, bnv);

    // Layer 2
    k_gemm_mma<64><<<gb, 256>>>(px1, W2, as2, ad2);
    k_agg<2><<<ab, 256>>>(b2, nullptr, nullptr, nullptr, nullptr);

    // Final projection on JK-max output
    k_gemmf<<<fb, 160>>>(px1, Wf, bf, out);
}